// round 13
// baseline (speedup 1.0000x reference)
#include <cuda_runtime.h>
#include <cuda_fp16.h>

#define NN 100000
#define DD 256
#define EE 300000
#define NB 98   // ceil(NN/1024)

typedef unsigned long long ull;

// ---------------- scratch (fp16 activations) ----------------
__device__ __align__(16) __half g_x0h[NN * DD];
__device__ __align__(16) __half g_x1h[NN * DD];
__device__ __align__(16) __half g_x2h[NN * DD];
__device__ int   g_degi[NN];
__device__ float g_invdeg[NN];
__device__ int   g_off[NN];
__device__ int   g_cursor[NN];
__device__ int   g_csr[EE];
__device__ int   g_src[EE];
__device__ int   g_dst[EE];
__device__ int   g_is64;
__device__ int   g_bsum[NB];
__device__ __align__(16) __half g_bh[3 * 256 * 512];   // W fp16 all layers: [layer][m][k]

__device__ __forceinline__ unsigned h2u(__half2 v) {
    unsigned r;
    memcpy(&r, &v, 4);
    return r;
}

// ---------------- index dtype detection ----------------
__global__ void detect_kernel(const unsigned int* __restrict__ w) {
    if (threadIdx.x == 0 && blockIdx.x == 0) {
        unsigned int s = 0;
        #pragma unroll 1
        for (int i = 1; i < 256; i += 2) s |= w[i];
        g_is64 = (s == 0u) ? 1 : 0;
    }
}

// ---------------- fused prep: convert edges | zero deg | x0->fp16 | convw x3 ----------------
#define PB_CONV 1172     // ceil(EE/256)
#define PB_ZERO 391      // ceil(NN/256)
#define PB_CVT0 12500    // NN*DD/8/256
#define PB_CONVW 1536    // 3 * 131072/256
#define PB_TOTAL (PB_CONV + PB_ZERO + PB_CVT0 + PB_CONVW)

__global__ __launch_bounds__(256) void prep_kernel(
    const void* __restrict__ edge, const float* __restrict__ x0,
    const float* __restrict__ Wl0, const float* __restrict__ Wr0,
    const float* __restrict__ Wl1, const float* __restrict__ Wr1,
    const float* __restrict__ Wl2, const float* __restrict__ Wr2)
{
    int b = blockIdx.x;
    int t = threadIdx.x;
    if (b < PB_CONV) {                      // edge convert
        int e = b * 256 + t;
        if (e < EE) {
            if (g_is64) {
                const long long* p = (const long long*)edge;
                g_src[e] = (int)p[e];
                g_dst[e] = (int)p[EE + e];
            } else {
                const int* p = (const int*)edge;
                g_src[e] = p[e];
                g_dst[e] = p[EE + e];
            }
        }
        return;
    }
    b -= PB_CONV;
    if (b < PB_ZERO) {                      // zero degree
        int n = b * 256 + t;
        if (n < NN) g_degi[n] = 0;
        return;
    }
    b -= PB_ZERO;
    if (b < PB_CVT0) {                      // x0 -> fp16
        int i = b * 256 + t;
        const float4* p = (const float4*)x0 + (size_t)i * 2;
        float4 v0 = p[0];
        float4 v1 = p[1];
        uint4 o;
        o.x = h2u(__floats2half2_rn(v0.x, v0.y));
        o.y = h2u(__floats2half2_rn(v0.z, v0.w));
        o.z = h2u(__floats2half2_rn(v1.x, v1.y));
        o.w = h2u(__floats2half2_rn(v1.z, v1.w));
        ((uint4*)g_x0h)[i] = o;
        return;
    }
    b -= PB_CVT0;                           // weight convert, 3 layers
    int layer = b >> 9;
    int i = ((b & 511) << 8) + t;           // 0..131071
    const float* Wl = (layer == 0) ? Wl0 : ((layer == 1) ? Wl1 : Wl2);
    const float* Wr = (layer == 0) ? Wr0 : ((layer == 1) ? Wr1 : Wr2);
    int m = i >> 9, k = i & 511;
    float w = (k < 256) ? Wl[m * 256 + k] : Wr[m * 256 + (k - 256)];
    g_bh[layer * 131072 + i] = __float2half_rn(w);
}

// ---------------- degree + CSR build ----------------
__global__ void deg_kernel() {
    int e = blockIdx.x * blockDim.x + threadIdx.x;
    if (e < EE) atomicAdd(&g_degi[g_dst[e]], 1);
}

__global__ void scanA_kernel() {
    __shared__ int sh[1024];
    int t = threadIdx.x;
    int n = blockIdx.x * 1024 + t;
    int v = (n < NN) ? g_degi[n] : 0;
    if (n < NN) g_invdeg[n] = 1.0f / fmaxf((float)v, 1.0f);
    sh[t] = v;
    __syncthreads();
    #pragma unroll
    for (int off = 512; off > 0; off >>= 1) {
        if (t < off) sh[t] += sh[t + off];
        __syncthreads();
    }
    if (t == 0) g_bsum[blockIdx.x] = sh[0];
}

// per-block exclusive scan; block base computed in-block from g_bsum
__global__ void scanC_kernel() {
    __shared__ int sh[1024];
    int t = threadIdx.x;
    sh[t] = (t < NB && t < blockIdx.x) ? g_bsum[t] : 0;
    __syncthreads();
    #pragma unroll
    for (int off = 512; off > 0; off >>= 1) {
        if (t < off) sh[t] += sh[t + off];
        __syncthreads();
    }
    int base = sh[0];
    __syncthreads();
    int n = blockIdx.x * 1024 + t;
    int v = (n < NN) ? g_degi[n] : 0;
    sh[t] = v;
    __syncthreads();
    #pragma unroll
    for (int off = 1; off < 1024; off <<= 1) {
        int x = (t >= off) ? sh[t - off] : 0;
        __syncthreads();
        sh[t] += x;
        __syncthreads();
    }
    if (n < NN) {
        int ex = base + sh[t] - v;
        g_off[n] = ex;
        g_cursor[n] = ex;
    }
}

__global__ void fill_kernel() {
    int e = blockIdx.x * blockDim.x + threadIdx.x;
    if (e >= EE) return;
    int pos = atomicAdd(&g_cursor[g_dst[e]], 1);
    g_csr[pos] = g_src[e];
}

// ---------------- mma / async-copy helpers (baseline PTX) ----------------
__device__ __forceinline__ unsigned sm_u32(const void* p) {
    unsigned r;
    asm("{ .reg .u64 t; cvta.to.shared.u64 t, %1; cvt.u32.u64 %0, t; }" : "=r"(r) : "l"(p));
    return r;
}
__device__ __forceinline__ void sts128(unsigned a, unsigned x, unsigned y, unsigned z, unsigned w) {
    asm volatile("st.shared.v4.b32 [%0], {%1,%2,%3,%4};" :: "r"(a), "r"(x), "r"(y), "r"(z), "r"(w));
}
__device__ __forceinline__ void cpasync16(unsigned smem, const void* g) {
    asm volatile("cp.async.cg.shared.global [%0], [%1], 16;" :: "r"(smem), "l"(g));
}
__device__ __forceinline__ void cpcommit() { asm volatile("cp.async.commit_group;"); }
__device__ __forceinline__ void cpwait0() { asm volatile("cp.async.wait_group 0;"); }
__device__ __forceinline__ void ldsm4(unsigned& r0, unsigned& r1, unsigned& r2, unsigned& r3, unsigned a) {
    asm volatile("ldmatrix.sync.aligned.m8n8.x4.shared.b16 {%0,%1,%2,%3}, [%4];"
                 : "=r"(r0), "=r"(r1), "=r"(r2), "=r"(r3) : "r"(a));
}
__device__ __forceinline__ void mma16816(float* c, const unsigned* a, unsigned b0, unsigned b1) {
    asm volatile(
        "mma.sync.aligned.m16n8k16.row.col.f32.f16.f16.f32 "
        "{%0,%1,%2,%3}, {%4,%5,%6,%7}, {%8,%9}, {%0,%1,%2,%3};"
        : "+f"(c[0]), "+f"(c[1]), "+f"(c[2]), "+f"(c[3])
        : "r"(a[0]), "r"(a[1]), "r"(a[2]), "r"(a[3]), "r"(b0), "r"(b1));
}

// smem layout: rows padded to 80B (gcd(80,128)=16 -> conflict-free ldmatrix)
#define ASTR 80
#define SM_A 10240             // 128 rows * 80B (one 32-k chunk)
#define SM_B 20480             // 256 rows * 80B
#define PAGG_SZ (8 * SM_A)     // persistent agg panel: 8 chunks = 81920
#define PSTG PAGG_SZ           // staged region starts after panel
#define SM_STG (SM_A + SM_B)   // one stage: A|B = 30720
#define SM_TOT (PAGG_SZ + 2 * SM_STG)   // 143360

// ---------------- fused aggregate+GEMM ----------------
// Per CTA: gather-mean 128 rows' neighborhoods into smem panel (K cols 0..255),
// then K=512 GEMM: chunks 0..7 read panel, 8..15 stream x. bias+relu epilogue.
__global__ __launch_bounds__(512) void gemm_mma_kernel(
    int xsel, float* __restrict__ oext, int osel,
    const float* __restrict__ bias, int do_relu, int layer)
{
    extern __shared__ char smem[];
    const __half* xin = (xsel == 0) ? g_x0h : ((xsel == 1) ? g_x1h : g_x2h);
    __half* outh = (osel == 1) ? g_x1h : g_x2h;
    const __half* bw = g_bh + layer * 131072;

    const unsigned su = sm_u32(smem);

    const int tid = threadIdx.x;
    const int wid = tid >> 5;
    const int lane = tid & 31;
    const int wm = wid & 1;
    const int wn = wid >> 1;
    const int row0 = blockIdx.x * 128;

    // ---- prologue: gather-mean aggregation into persistent panel ----
    // warp w handles rows w*8 .. w*8+7; lane covers cols [lane*8, lane*8+8)
    {
        const unsigned pbase = su + (unsigned)((lane >> 2) * SM_A + (lane & 3) * 16);
        #pragma unroll 1
        for (int rr = 0; rr < 8; rr++) {
            const int rl = wid * 8 + rr;
            const int r = row0 + rl;
            int st = 0, cnt = 0;
            float id = 0.f;
            if (r < NN) { st = g_off[r]; cnt = g_degi[r]; id = g_invdeg[r]; }
            float a[8] = {0.f, 0.f, 0.f, 0.f, 0.f, 0.f, 0.f, 0.f};
            #pragma unroll 1
            for (int i = 0; i < cnt; i++) {
                int s = g_csr[st + i];
                uint4 v = *(const uint4*)(xin + (size_t)s * DD + lane * 8);
                __half2 h;
                float2 f;
                memcpy(&h, &v.x, 4); f = __half22float2(h); a[0] += f.x; a[1] += f.y;
                memcpy(&h, &v.y, 4); f = __half22float2(h); a[2] += f.x; a[3] += f.y;
                memcpy(&h, &v.z, 4); f = __half22float2(h); a[4] += f.x; a[5] += f.y;
                memcpy(&h, &v.w, 4); f = __half22float2(h); a[6] += f.x; a[7] += f.y;
            }
            uint4 o;
            o.x = h2u(__floats2half2_rn(a[0] * id, a[1] * id));
            o.y = h2u(__floats2half2_rn(a[2] * id, a[3] * id));
            o.z = h2u(__floats2half2_rn(a[4] * id, a[5] * id));
            o.w = h2u(__floats2half2_rn(a[6] * id, a[7] * id));
            sts128(pbase + (unsigned)(rl * ASTR), o.x, o.y, o.z, o.w);
        }
    }

    // ---- mainloop geometry ----
    const int arow = tid >> 2;
    const int akq = tid & 3;
    const int gr = row0 + arow;
    const bool rok = gr < NN;
    const __half* xrow = xin + (size_t)(rok ? gr : 0) * DD;

    const int brow = tid >> 1;
    const int bkh = (tid & 1) * 16;

    const unsigned aoff = (unsigned)((wm * 64 + (lane & 15)) * ASTR + (lane >> 4) * 16);
    const unsigned boff = (unsigned)((wn * 32 + ((lane >> 4) & 1) * 8 + (lane & 7)) * ASTR
                                     + ((lane >> 3) & 1) * 16);

    float acc[4][4][4];
    #pragma unroll
    for (int i = 0; i < 4; i++)
        #pragma unroll
        for (int j = 0; j < 4; j++)
            #pragma unroll
            for (int q = 0; q < 4; q++) acc[i][j][q] = 0.f;

    uint4 pa;   // prefetched A chunk (x side only)

    auto ldA = [&](int ck) {
        const __half* s = xrow + (ck & 7) * 32 + akq * 8;
        if (rok) pa = *(const uint4*)s;
        else pa = make_uint4(0u, 0u, 0u, 0u);
    };
    auto stsA = [&](int stg) {
        unsigned base = su + PSTG + (unsigned)stg * SM_STG;
        unsigned off = (unsigned)(arow * ASTR + akq * 16);
        sts128(base + off, pa.x, pa.y, pa.z, pa.w);
    };
    auto cpB = [&](int ck, int stg) {
        unsigned base = su + PSTG + (unsigned)stg * SM_STG + SM_A;
        unsigned off = (unsigned)(brow * ASTR + bkh * 2);
        size_t go = (size_t)brow * 512 + ck * 32 + bkh;
        cpasync16(base + off, bw + go);
        cpasync16(base + off + 16, bw + go + 8);
        cpcommit();
    };

    // pipeline prologue: B for chunk 0 in flight
    cpB(0, 0);

    #pragma unroll 1
    for (int ck = 0; ck < 16; ck++) {
        const int s = ck & 1;
        cpwait0();
        __syncthreads();   // also orders the agg-panel writes before first ldsm

        if (ck < 15) {
            if (ck + 1 >= 8) stsA(s ^ 1);   // x-side A arrives via register prefetch
            cpB(ck + 1, s ^ 1);
        }
        if (ck < 14 && ck + 2 >= 8) ldA(ck + 2);

        const unsigned suA = (ck < 8) ? (su + (unsigned)ck * SM_A)
                                      : (su + PSTG + (unsigned)s * SM_STG);
        const unsigned suB = su + PSTG + (unsigned)s * SM_STG + SM_A;

        #pragma unroll
        for (int ks = 0; ks < 2; ks++) {
            const unsigned kb = (unsigned)(ks * 32);
            unsigned bh[4][2];
            #pragma unroll
            for (int p = 0; p < 2; p++) {
                ldsm4(bh[2 * p][0], bh[2 * p][1], bh[2 * p + 1][0], bh[2 * p + 1][1],
                      suB + boff + p * (16 * ASTR) + kb);
            }
            #pragma unroll
            for (int mi = 0; mi < 4; mi++) {
                unsigned af[4];
                ldsm4(af[0], af[1], af[2], af[3], suA + aoff + mi * (16 * ASTR) + kb);
                #pragma unroll
                for (int ni = 0; ni < 4; ni++) mma16816(acc[mi][ni], af, bh[ni][0], bh[ni][1]);
            }
        }
    }

    // ---- epilogue: bias + relu; fp32 for final layer, fp16 for intermediates ----
    const int gr2 = lane >> 2;
    const int gc2 = (lane & 3) * 2;
    #pragma unroll
    for (int mi = 0; mi < 4; mi++) {
        const int rbase = row0 + wm * 64 + mi * 16 + gr2;
        #pragma unroll
        for (int h = 0; h < 2; h++) {
            const int r = rbase + h * 8;
            if (r < NN) {
                #pragma unroll
                for (int ni = 0; ni < 4; ni++) {
                    const int c = wn * 32 + ni * 8 + gc2;
                    float2 bv = *(const float2*)(bias + c);
                    float v0 = acc[mi][ni][h * 2 + 0] + bv.x;
                    float v1 = acc[mi][ni][h * 2 + 1] + bv.y;
                    if (do_relu) { v0 = fmaxf(v0, 0.f); v1 = fmaxf(v1, 0.f); }
                    if (osel == 0) {
                        *(float2*)(oext + (size_t)r * DD + c) = make_float2(v0, v1);
                    } else {
                        *(unsigned*)(outh + (size_t)r * DD + c) = h2u(__floats2half2_rn(v0, v1));
                    }
                }
            }
        }
    }
}

// ---------------- launcher ----------------
extern "C" void kernel_launch(void* const* d_in, const int* in_sizes, int n_in,
                              void* d_out, int out_size) {
    (void)in_sizes; (void)n_in; (void)out_size;
    const void* edge = d_in[0];
    const float* x0 = (const float*)d_in[1];
    const float* Wl[3] = {(const float*)d_in[2], (const float*)d_in[5], (const float*)d_in[8]};
    const float* Wr[3] = {(const float*)d_in[3], (const float*)d_in[6], (const float*)d_in[9]};
    const float* bb[3] = {(const float*)d_in[4], (const float*)d_in[7], (const float*)d_in[10]};
    float* out = (float*)d_out;

    static int smem_set = 0;
    if (!smem_set) {
        cudaFuncSetAttribute(gemm_mma_kernel, cudaFuncAttributeMaxDynamicSharedMemorySize, SM_TOT);
        smem_set = 1;
    }

    const int TB = 256;
    const int ecnt = (EE + TB - 1) / TB;
    const int ggrid = (NN + 127) / 128;

    detect_kernel<<<1, 32>>>((const unsigned int*)edge);
    prep_kernel<<<PB_TOTAL, TB>>>(edge, x0, Wl[0], Wr[0], Wl[1], Wr[1], Wl[2], Wr[2]);
    deg_kernel<<<ecnt, TB>>>();
    scanA_kernel<<<NB, 1024>>>();
    scanC_kernel<<<NB, 1024>>>();
    fill_kernel<<<ecnt, TB>>>();

    gemm_mma_kernel<<<ggrid, 512, SM_TOT>>>(0, nullptr, 1, bb[0], 1, 0);
    gemm_mma_kernel<<<ggrid, 512, SM_TOT>>>(1, nullptr, 2, bb[1], 1, 1);
    gemm_mma_kernel<<<ggrid, 512, SM_TOT>>>(2, out, 0, bb[2], 0, 2);
}

// round 14
// speedup vs baseline: 1.1874x; 1.1874x over previous
#include <cuda_runtime.h>
#include <cuda_fp16.h>

#define NN 100000
#define DD 256
#define EE 300000
#define NB 98   // ceil(NN/1024)

typedef unsigned long long ull;

// ---------------- scratch (fp16 activations) ----------------
__device__ __align__(16) __half g_x0h[NN * DD];
__device__ __align__(16) __half g_x1h[NN * DD];
__device__ __align__(16) __half g_x2h[NN * DD];
__device__ int   g_degi[NN];     // zero at load; re-zeroed by gemm3 tail each run
__device__ float g_invdeg[NN];
__device__ int   g_off[NN];
__device__ int   g_cursor[NN];
__device__ int   g_csr[EE];
__device__ int   g_src[EE];
__device__ int   g_dst[EE];
__device__ int   g_bsum[NB];
__device__ __align__(16) __half g_bh[3 * 256 * 512];   // W fp16 all layers: [layer][m][k]

__device__ __forceinline__ unsigned h2u(__half2 v) {
    unsigned r;
    memcpy(&r, &v, 4);
    return r;
}

// ---------------- prep_edge: inline dtype detect + edge convert + degree count ----------------
__global__ __launch_bounds__(256) void prep_edge_kernel(const void* __restrict__ edge) {
    __shared__ unsigned sdet;
    int t = threadIdx.x;
    if (t == 0) sdet = 0u;
    __syncthreads();
    if (t < 128) {
        unsigned v = ((const unsigned*)edge)[2 * t + 1];
        if (v) atomicOr(&sdet, 1u);
    }
    __syncthreads();
    const bool is64 = (sdet == 0u);

    int e = blockIdx.x * 256 + t;
    if (e >= EE) return;
    int s, d;
    if (is64) {
        const long long* p = (const long long*)edge;
        s = (int)p[e];
        d = (int)p[EE + e];
    } else {
        const int* p = (const int*)edge;
        s = p[e];
        d = p[EE + e];
    }
    g_src[e] = s;
    g_dst[e] = d;
    atomicAdd(&g_degi[d], 1);
}

// ---------------- prep_data: x0->fp16 | convw x3 (independent branch) ----------------
#define PD_CVT0 12500    // NN*DD/8/256
#define PD_CONVW 1536    // 3 * 131072/256
#define PD_TOTAL (PD_CVT0 + PD_CONVW)

__global__ __launch_bounds__(256) void prep_data_kernel(
    const float* __restrict__ x0,
    const float* __restrict__ Wl0, const float* __restrict__ Wr0,
    const float* __restrict__ Wl1, const float* __restrict__ Wr1,
    const float* __restrict__ Wl2, const float* __restrict__ Wr2)
{
    int b = blockIdx.x;
    int t = threadIdx.x;
    if (b < PD_CVT0) {                      // x0 -> fp16
        int i = b * 256 + t;
        const float4* p = (const float4*)x0 + (size_t)i * 2;
        float4 v0 = p[0];
        float4 v1 = p[1];
        uint4 o;
        o.x = h2u(__floats2half2_rn(v0.x, v0.y));
        o.y = h2u(__floats2half2_rn(v0.z, v0.w));
        o.z = h2u(__floats2half2_rn(v1.x, v1.y));
        o.w = h2u(__floats2half2_rn(v1.z, v1.w));
        ((uint4*)g_x0h)[i] = o;
        return;
    }
    b -= PD_CVT0;                           // weight convert, 3 layers
    int layer = b >> 9;
    int i = ((b & 511) << 8) + t;           // 0..131071
    const float* Wl = (layer == 0) ? Wl0 : ((layer == 1) ? Wl1 : Wl2);
    const float* Wr = (layer == 0) ? Wr0 : ((layer == 1) ? Wr1 : Wr2);
    int m = i >> 9, k = i & 511;
    float w = (k < 256) ? Wl[m * 256 + k] : Wr[m * 256 + (k - 256)];
    g_bh[layer * 131072 + i] = __float2half_rn(w);
}

// ---------------- CSR build ----------------
__global__ void scanA_kernel() {
    __shared__ int sh[1024];
    int t = threadIdx.x;
    int n = blockIdx.x * 1024 + t;
    int v = (n < NN) ? g_degi[n] : 0;
    if (n < NN) g_invdeg[n] = 1.0f / fmaxf((float)v, 1.0f);
    sh[t] = v;
    __syncthreads();
    #pragma unroll
    for (int off = 512; off > 0; off >>= 1) {
        if (t < off) sh[t] += sh[t + off];
        __syncthreads();
    }
    if (t == 0) g_bsum[blockIdx.x] = sh[0];
}

__global__ void scanC_kernel() {
    __shared__ int sh[1024];
    int t = threadIdx.x;
    sh[t] = (t < NB && t < blockIdx.x) ? g_bsum[t] : 0;
    __syncthreads();
    #pragma unroll
    for (int off = 512; off > 0; off >>= 1) {
        if (t < off) sh[t] += sh[t + off];
        __syncthreads();
    }
    int base = sh[0];
    __syncthreads();
    int n = blockIdx.x * 1024 + t;
    int v = (n < NN) ? g_degi[n] : 0;
    sh[t] = v;
    __syncthreads();
    #pragma unroll
    for (int off = 1; off < 1024; off <<= 1) {
        int x = (t >= off) ? sh[t - off] : 0;
        __syncthreads();
        sh[t] += x;
        __syncthreads();
    }
    if (n < NN) {
        int ex = base + sh[t] - v;
        g_off[n] = ex;
        g_cursor[n] = ex;
    }
}

__global__ void fill_kernel() {
    int e = blockIdx.x * blockDim.x + threadIdx.x;
    if (e >= EE) return;
    int pos = atomicAdd(&g_cursor[g_dst[e]], 1);
    g_csr[pos] = g_src[e];
}

// ---------------- aggregation: warp per node, shfl-batched indices + 2-way ILP ----------------
__device__ __forceinline__ void accum_row(const __half* __restrict__ xin, int s, int lane, float* a) {
    uint4 v = *(const uint4*)(xin + (size_t)s * DD + lane * 8);
    __half2 h;
    float2 f;
    memcpy(&h, &v.x, 4); f = __half22float2(h); a[0] += f.x; a[1] += f.y;
    memcpy(&h, &v.y, 4); f = __half22float2(h); a[2] += f.x; a[3] += f.y;
    memcpy(&h, &v.z, 4); f = __half22float2(h); a[4] += f.x; a[5] += f.y;
    memcpy(&h, &v.w, 4); f = __half22float2(h); a[6] += f.x; a[7] += f.y;
}

__device__ __align__(16) __half g_acch[NN * DD];

__global__ __launch_bounds__(256) void aggregate_kernel(int xsel) {
    const __half* xin = (xsel == 0) ? g_x0h : ((xsel == 1) ? g_x1h : g_x2h);
    int warp = (blockIdx.x * blockDim.x + threadIdx.x) >> 5;
    if (warp >= NN) return;
    int lane = threadIdx.x & 31;
    int start = g_off[warp];
    int cnt = g_degi[warp];
    float a[8] = {0.f, 0.f, 0.f, 0.f, 0.f, 0.f, 0.f, 0.f};
    float b[8] = {0.f, 0.f, 0.f, 0.f, 0.f, 0.f, 0.f, 0.f};
    #pragma unroll 1
    for (int base = 0; base < cnt; base += 32) {
        int m = min(cnt - base, 32);
        int idx = (lane < m) ? g_csr[start + base + lane] : 0;
        int j = 0;
        #pragma unroll 1
        for (; j + 2 <= m; j += 2) {
            int s0 = __shfl_sync(0xffffffffu, idx, j);
            int s1 = __shfl_sync(0xffffffffu, idx, j + 1);
            accum_row(xin, s0, lane, a);
            accum_row(xin, s1, lane, b);
        }
        if (j < m) {
            int s0 = __shfl_sync(0xffffffffu, idx, j);
            accum_row(xin, s0, lane, a);
        }
    }
    float id = g_invdeg[warp];
    uint4 o;
    o.x = h2u(__floats2half2_rn((a[0] + b[0]) * id, (a[1] + b[1]) * id));
    o.y = h2u(__floats2half2_rn((a[2] + b[2]) * id, (a[3] + b[3]) * id));
    o.z = h2u(__floats2half2_rn((a[4] + b[4]) * id, (a[5] + b[5]) * id));
    o.w = h2u(__floats2half2_rn((a[6] + b[6]) * id, (a[7] + b[7]) * id));
    *(uint4*)(g_acch + (size_t)warp * DD + lane * 8) = o;
}

// ---------------- mma / async-copy helpers (baseline PTX) ----------------
__device__ __forceinline__ unsigned sm_u32(const void* p) {
    unsigned r;
    asm("{ .reg .u64 t; cvta.to.shared.u64 t, %1; cvt.u32.u64 %0, t; }" : "=r"(r) : "l"(p));
    return r;
}
__device__ __forceinline__ void sts128(unsigned a, unsigned x, unsigned y, unsigned z, unsigned w) {
    asm volatile("st.shared.v4.b32 [%0], {%1,%2,%3,%4};" :: "r"(a), "r"(x), "r"(y), "r"(z), "r"(w));
}
__device__ __forceinline__ void cpasync16(unsigned smem, const void* g) {
    asm volatile("cp.async.cg.shared.global [%0], [%1], 16;" :: "r"(smem), "l"(g));
}
__device__ __forceinline__ void cpcommit() { asm volatile("cp.async.commit_group;"); }
__device__ __forceinline__ void cpwait0() { asm volatile("cp.async.wait_group 0;"); }
__device__ __forceinline__ void ldsm4(unsigned& r0, unsigned& r1, unsigned& r2, unsigned& r3, unsigned a) {
    asm volatile("ldmatrix.sync.aligned.m8n8.x4.shared.b16 {%0,%1,%2,%3}, [%4];"
                 : "=r"(r0), "=r"(r1), "=r"(r2), "=r"(r3) : "r"(a));
}
__device__ __forceinline__ void mma16816(float* c, const unsigned* a, unsigned b0, unsigned b1) {
    asm volatile(
        "mma.sync.aligned.m16n8k16.row.col.f32.f16.f16.f32 "
        "{%0,%1,%2,%3}, {%4,%5,%6,%7}, {%8,%9}, {%0,%1,%2,%3};"
        : "+f"(c[0]), "+f"(c[1]), "+f"(c[2]), "+f"(c[3])
        : "r"(a[0]), "r"(a[1]), "r"(a[2]), "r"(a[3]), "r"(b0), "r"(b1));
}

// smem layout: rows padded to 80B (gcd(80,128)=16 -> conflict-free ldmatrix)
#define ASTR 80
#define SM_A 10240             // 128 rows * 80B
#define SM_B 20480             // 256 rows * 80B
#define SM_STG (SM_A + SM_B)        // one stage: A|B = 30720
#define SM_TOT (2*SM_STG)           // double buffered = 61440

// ---------------- fused layer GEMM (round-9 proven: LDG-prefetch A + cp.async B) ----------------
__global__ __launch_bounds__(512) void gemm_mma_kernel(
    int xsel, float* __restrict__ oext, int osel,
    const float* __restrict__ bias, int do_relu, int layer, int zero_deg)
{
    extern __shared__ char smem[];
    const __half* xin = (xsel == 0) ? g_x0h : ((xsel == 1) ? g_x1h : g_x2h);
    __half* outh = (osel == 1) ? g_x1h : g_x2h;
    const __half* bw = g_bh + layer * 131072;

    const unsigned su = sm_u32(smem);

    const int tid = threadIdx.x;
    const int wid = tid >> 5;
    const int lane = tid & 31;
    const int wm = wid & 1;
    const int wn = wid >> 1;
    const int row0 = blockIdx.x * 128;

    // A loader geometry: 4 threads per row, 8 halfs (16B) each
    const int arow = tid >> 2;
    const int akq = tid & 3;
    const int gr = row0 + arow;
    const bool rok = gr < NN;
    const __half* aggrow = g_acch + (size_t)(rok ? gr : 0) * DD;
    const __half* xrow = xin + (size_t)(rok ? gr : 0) * DD;

    // B loader geometry (cp.async)
    const int brow = tid >> 1;
    const int bkh = (tid & 1) * 16;

    const unsigned aoff = (unsigned)((wm * 64 + (lane & 15)) * ASTR + (lane >> 4) * 16);
    const unsigned boff = (unsigned)((wn * 32 + ((lane >> 4) & 1) * 8 + (lane & 7)) * ASTR
                                     + ((lane >> 3) & 1) * 16);

    float acc[4][4][4];
    #pragma unroll
    for (int i = 0; i < 4; i++)
        #pragma unroll
        for (int j = 0; j < 4; j++)
            #pragma unroll
            for (int q = 0; q < 4; q++) acc[i][j][q] = 0.f;

    uint4 pa;   // prefetched A chunk (8 fp16)

    auto ldA = [&](int ck) {
        const int side = ck >> 3;
        const __half* s = (side ? xrow : aggrow) + (ck & 7) * 32 + akq * 8;
        if (rok) pa = *(const uint4*)s;
        else pa = make_uint4(0u, 0u, 0u, 0u);
    };
    auto stsA = [&](int stg) {
        unsigned base = su + (unsigned)stg * SM_STG;
        unsigned off = (unsigned)(arow * ASTR + akq * 16);
        sts128(base + off, pa.x, pa.y, pa.z, pa.w);
    };
    auto cpB = [&](int ck, int stg) {
        unsigned base = su + (unsigned)stg * SM_STG + SM_A;
        unsigned off = (unsigned)(brow * ASTR + bkh * 2);
        size_t go = (size_t)brow * 512 + ck * 32 + bkh;
        cpasync16(base + off, bw + go);
        cpasync16(base + off + 16, bw + go + 8);
        cpcommit();
    };

    // prologue
    ldA(0);
    stsA(0);
    cpB(0, 0);
    ldA(1);

    #pragma unroll 1
    for (int ck = 0; ck < 16; ck++) {
        const int s = ck & 1;
        cpwait0();
        __syncthreads();

        if (ck < 15) {
            stsA(s ^ 1);
            cpB(ck + 1, s ^ 1);
        }
        if (ck < 14) ldA(ck + 2);

        const unsigned sbase = su + (unsigned)s * SM_STG;
        const unsigned suA = sbase;
        const unsigned suB = sbase + SM_A;

        #pragma unroll
        for (int ks = 0; ks < 2; ks++) {
            const unsigned kb = (unsigned)(ks * 32);
            unsigned bh[4][2];
            #pragma unroll
            for (int p = 0; p < 2; p++) {
                ldsm4(bh[2 * p][0], bh[2 * p][1], bh[2 * p + 1][0], bh[2 * p + 1][1],
                      suB + boff + p * (16 * ASTR) + kb);
            }
            #pragma unroll
            for (int mi = 0; mi < 4; mi++) {
                unsigned af[4];
                ldsm4(af[0], af[1], af[2], af[3], suA + aoff + mi * (16 * ASTR) + kb);
                #pragma unroll
                for (int ni = 0; ni < 4; ni++) mma16816(acc[mi][ni], af, bh[ni][0], bh[ni][1]);
            }
        }
    }

    // ---- epilogue: bias + relu; fp32 for final layer, fp16 for intermediates ----
    const int gr2 = lane >> 2;
    const int gc2 = (lane & 3) * 2;
    #pragma unroll
    for (int mi = 0; mi < 4; mi++) {
        const int rbase = row0 + wm * 64 + mi * 16 + gr2;
        #pragma unroll
        for (int h = 0; h < 2; h++) {
            const int r = rbase + h * 8;
            if (r < NN) {
                #pragma unroll
                for (int ni = 0; ni < 4; ni++) {
                    const int c = wn * 32 + ni * 8 + gc2;
                    float2 bv = *(const float2*)(bias + c);
                    float v0 = acc[mi][ni][h * 2 + 0] + bv.x;
                    float v1 = acc[mi][ni][h * 2 + 1] + bv.y;
                    if (do_relu) { v0 = fmaxf(v0, 0.f); v1 = fmaxf(v1, 0.f); }
                    if (osel == 0) {
                        *(float2*)(oext + (size_t)r * DD + c) = make_float2(v0, v1);
                    } else {
                        *(unsigned*)(outh + (size_t)r * DD + c) = h2u(__floats2half2_rn(v0, v1));
                    }
                }
            }
        }
    }

    // last layer: re-zero degree counters for the next graph replay
    if (zero_deg && tid < 128) {
        int n = row0 + tid;
        if (n < NN) g_degi[n] = 0;
    }
}

// ---------------- launcher ----------------
extern "C" void kernel_launch(void* const* d_in, const int* in_sizes, int n_in,
                              void* d_out, int out_size) {
    (void)in_sizes; (void)n_in; (void)out_size;
    const void* edge = d_in[0];
    const float* x0 = (const float*)d_in[1];
    const float* Wl[3] = {(const float*)d_in[2], (const float*)d_in[5], (const float*)d_in[8]};
    const float* Wr[3] = {(const float*)d_in[3], (const float*)d_in[6], (const float*)d_in[9]};
    const float* bb[3] = {(const float*)d_in[4], (const float*)d_in[7], (const float*)d_in[10]};
    float* out = (float*)d_out;

    static int inited = 0;
    static cudaStream_t s1;
    static cudaEvent_t evFork, evJoin;
    if (!inited) {
        cudaFuncSetAttribute(gemm_mma_kernel, cudaFuncAttributeMaxDynamicSharedMemorySize, SM_TOT);
        cudaStreamCreateWithFlags(&s1, cudaStreamNonBlocking);
        cudaEventCreateWithFlags(&evFork, cudaEventDisableTiming);
        cudaEventCreateWithFlags(&evJoin, cudaEventDisableTiming);
        inited = 1;
    }

    const int TB = 256;
    const int ecnt = (EE + TB - 1) / TB;
    const int ggrid = (NN + 127) / 128;
    const int agrid = (NN * 32 + TB - 1) / TB;

    // fork: data conversion branch runs concurrently with edge/CSR chain
    cudaEventRecord(evFork, 0);
    cudaStreamWaitEvent(s1, evFork, 0);
    prep_data_kernel<<<PD_TOTAL, TB, 0, s1>>>(x0, Wl[0], Wr[0], Wl[1], Wr[1], Wl[2], Wr[2]);
    cudaEventRecord(evJoin, s1);

    // main chain (default stream)
    prep_edge_kernel<<<ecnt, TB>>>(edge);
    scanA_kernel<<<NB, 1024>>>();
    scanC_kernel<<<NB, 1024>>>();
    fill_kernel<<<ecnt, TB>>>();

    cudaStreamWaitEvent(0, evJoin, 0);   // join: agg1 needs x0h, gemm needs weights

    aggregate_kernel<<<agrid, TB>>>(0);
    gemm_mma_kernel<<<ggrid, 512, SM_TOT>>>(0, nullptr, 1, bb[0], 1, 0, 0);

    aggregate_kernel<<<agrid, TB>>>(1);
    gemm_mma_kernel<<<ggrid, 512, SM_TOT>>>(1, nullptr, 2, bb[1], 1, 1, 0);

    aggregate_kernel<<<agrid, TB>>>(2);
    gemm_mma_kernel<<<ggrid, 512, SM_TOT>>>(2, out, 0, bb[2], 0, 2, 1);
}

// round 15
// speedup vs baseline: 1.2000x; 1.0106x over previous
#include <cuda_runtime.h>
#include <cuda_fp16.h>

#define NN 100000
#define DD 256
#define EE 300000
#define NB 98   // ceil(NN/1024)

typedef unsigned long long ull;

// ---------------- scratch (fp16 activations) ----------------
__device__ __align__(16) __half g_x0h[NN * DD];
__device__ __align__(16) __half g_x1h[NN * DD];
__device__ __align__(16) __half g_x2h[NN * DD];
__device__ __align__(16) __half g_acch[NN * DD];
__device__ int   g_degi[NN];     // zero at load; re-zeroed by gemm3 tail each run
__device__ float g_invdeg[NN];
__device__ int   g_off[NN];
__device__ int   g_cursor[NN];
__device__ int   g_csr[EE];
__device__ int   g_src[EE];
__device__ int   g_dst[EE];
__device__ int   g_bsum[NB];
__device__ int   g_scan_ctr;     // monotonic ticket counter (never reset)
__device__ __align__(16) __half g_bh[3 * 256 * 512];   // W fp16 all layers: [layer][m][k]

__device__ __forceinline__ unsigned h2u(__half2 v) {
    unsigned r;
    memcpy(&r, &v, 4);
    return r;
}

// ---------------- prep_edge: inline dtype detect + edge convert + degree count ----------------
__global__ __launch_bounds__(256) void prep_edge_kernel(const void* __restrict__ edge) {
    __shared__ unsigned sdet;
    int t = threadIdx.x;
    if (t == 0) sdet = 0u;
    __syncthreads();
    if (t < 128) {
        unsigned v = ((const unsigned*)edge)[2 * t + 1];
        if (v) atomicOr(&sdet, 1u);
    }
    __syncthreads();
    const bool is64 = (sdet == 0u);

    int e = blockIdx.x * 256 + t;
    if (e >= EE) return;
    int s, d;
    if (is64) {
        const long long* p = (const long long*)edge;
        s = (int)p[e];
        d = (int)p[EE + e];
    } else {
        const int* p = (const int*)edge;
        s = p[e];
        d = p[EE + e];
    }
    g_src[e] = s;
    g_dst[e] = d;
    atomicAdd(&g_degi[d], 1);
}

// ---------------- prep_data: x0->fp16 | convw x3 (independent branch) ----------------
#define PD_CVT0 12500    // NN*DD/8/256
#define PD_CONVW 1536    // 3 * 131072/256
#define PD_TOTAL (PD_CVT0 + PD_CONVW)

__global__ __launch_bounds__(256) void prep_data_kernel(
    const float* __restrict__ x0,
    const float* __restrict__ Wl0, const float* __restrict__ Wr0,
    const float* __restrict__ Wl1, const float* __restrict__ Wr1,
    const float* __restrict__ Wl2, const float* __restrict__ Wr2)
{
    int b = blockIdx.x;
    int t = threadIdx.x;
    if (b < PD_CVT0) {                      // x0 -> fp16
        int i = b * 256 + t;
        const float4* p = (const float4*)x0 + (size_t)i * 2;
        float4 v0 = p[0];
        float4 v1 = p[1];
        uint4 o;
        o.x = h2u(__floats2half2_rn(v0.x, v0.y));
        o.y = h2u(__floats2half2_rn(v0.z, v0.w));
        o.z = h2u(__floats2half2_rn(v1.x, v1.y));
        o.w = h2u(__floats2half2_rn(v1.z, v1.w));
        ((uint4*)g_x0h)[i] = o;
        return;
    }
    b -= PD_CVT0;                           // weight convert, 3 layers
    int layer = b >> 9;
    int i = ((b & 511) << 8) + t;           // 0..131071
    const float* Wl = (layer == 0) ? Wl0 : ((layer == 1) ? Wl1 : Wl2);
    const float* Wr = (layer == 0) ? Wr0 : ((layer == 1) ? Wr1 : Wr2);
    int m = i >> 9, k = i & 511;
    float w = (k < 256) ? Wl[m * 256 + k] : Wr[m * 256 + (k - 256)];
    g_bh[layer * 131072 + i] = __float2half_rn(w);
}

// ---------------- fused CSR scan: block sums + ticket barrier + offsets ----------------
// 98 blocks x 1024 threads: all co-resident (<=148 SMs), so spin-wait is safe.
// Ticket counter is monotonic: at launch k, counter starts at k*NB exactly, so
// each block derives its round's target without any reset (graph-replay safe).
__global__ __launch_bounds__(1024) void scan_kernel() {
    __shared__ int sh[1024];
    __shared__ int s_target;
    int t = threadIdx.x;
    int n = blockIdx.x * 1024 + t;
    int v = (n < NN) ? g_degi[n] : 0;
    if (n < NN) g_invdeg[n] = 1.0f / fmaxf((float)v, 1.0f);

    // phase A: block sum -> g_bsum
    sh[t] = v;
    __syncthreads();
    #pragma unroll
    for (int off = 512; off > 0; off >>= 1) {
        if (t < off) sh[t] += sh[t + off];
        __syncthreads();
    }
    if (t == 0) {
        g_bsum[blockIdx.x] = sh[0];
        __threadfence();
        int ticket = atomicAdd(&g_scan_ctr, 1);          // arrival
        int target = (ticket / NB + 1) * NB;
        while (((volatile int*)&g_scan_ctr)[0] < target) { }   // spin till all arrive
        s_target = 1;
    }
    __syncthreads();
    __threadfence();   // acquire: g_bsum[*] now visible

    // phase B: base = sum of bsums before this block, then in-block inclusive scan
    sh[t] = (t < NB && t < (int)blockIdx.x) ? g_bsum[t] : 0;
    __syncthreads();
    #pragma unroll
    for (int off = 512; off > 0; off >>= 1) {
        if (t < off) sh[t] += sh[t + off];
        __syncthreads();
    }
    int base = sh[0];
    __syncthreads();
    sh[t] = v;
    __syncthreads();
    #pragma unroll
    for (int off = 1; off < 1024; off <<= 1) {
        int x = (t >= off) ? sh[t - off] : 0;
        __syncthreads();
        sh[t] += x;
        __syncthreads();
    }
    if (n < NN) {
        int ex = base + sh[t] - v;
        g_off[n] = ex;
        g_cursor[n] = ex;
    }
}

__global__ void fill_kernel() {
    int e = blockIdx.x * blockDim.x + threadIdx.x;
    if (e >= EE) return;
    int pos = atomicAdd(&g_cursor[g_dst[e]], 1);
    g_csr[pos] = g_src[e];
}

// ---------------- aggregation: warp per node, shfl-batched indices + 2-way ILP ----------------
__device__ __forceinline__ void accum_row(const __half* __restrict__ xin, int s, int lane, float* a) {
    uint4 v = *(const uint4*)(xin + (size_t)s * DD + lane * 8);
    __half2 h;
    float2 f;
    memcpy(&h, &v.x, 4); f = __half22float2(h); a[0] += f.x; a[1] += f.y;
    memcpy(&h, &v.y, 4); f = __half22float2(h); a[2] += f.x; a[3] += f.y;
    memcpy(&h, &v.z, 4); f = __half22float2(h); a[4] += f.x; a[5] += f.y;
    memcpy(&h, &v.w, 4); f = __half22float2(h); a[6] += f.x; a[7] += f.y;
}

__global__ __launch_bounds__(256) void aggregate_kernel(int xsel) {
    const __half* xin = (xsel == 0) ? g_x0h : ((xsel == 1) ? g_x1h : g_x2h);
    int warp = (blockIdx.x * blockDim.x + threadIdx.x) >> 5;
    if (warp >= NN) return;
    int lane = threadIdx.x & 31;
    int start = g_off[warp];
    int cnt = g_degi[warp];
    float a[8] = {0.f, 0.f, 0.f, 0.f, 0.f, 0.f, 0.f, 0.f};
    float b[8] = {0.f, 0.f, 0.f, 0.f, 0.f, 0.f, 0.f, 0.f};
    #pragma unroll 1
    for (int base = 0; base < cnt; base += 32) {
        int m = min(cnt - base, 32);
        int idx = (lane < m) ? g_csr[start + base + lane] : 0;
        int j = 0;
        #pragma unroll 1
        for (; j + 2 <= m; j += 2) {
            int s0 = __shfl_sync(0xffffffffu, idx, j);
            int s1 = __shfl_sync(0xffffffffu, idx, j + 1);
            accum_row(xin, s0, lane, a);
            accum_row(xin, s1, lane, b);
        }
        if (j < m) {
            int s0 = __shfl_sync(0xffffffffu, idx, j);
            accum_row(xin, s0, lane, a);
        }
    }
    float id = g_invdeg[warp];
    uint4 o;
    o.x = h2u(__floats2half2_rn((a[0] + b[0]) * id, (a[1] + b[1]) * id));
    o.y = h2u(__floats2half2_rn((a[2] + b[2]) * id, (a[3] + b[3]) * id));
    o.z = h2u(__floats2half2_rn((a[4] + b[4]) * id, (a[5] + b[5]) * id));
    o.w = h2u(__floats2half2_rn((a[6] + b[6]) * id, (a[7] + b[7]) * id));
    *(uint4*)(g_acch + (size_t)warp * DD + lane * 8) = o;
}

// ---------------- mma / async-copy helpers (baseline PTX) ----------------
__device__ __forceinline__ unsigned sm_u32(const void* p) {
    unsigned r;
    asm("{ .reg .u64 t; cvta.to.shared.u64 t, %1; cvt.u32.u64 %0, t; }" : "=r"(r) : "l"(p));
    return r;
}
__device__ __forceinline__ void sts128(unsigned a, unsigned x, unsigned y, unsigned z, unsigned w) {
    asm volatile("st.shared.v4.b32 [%0], {%1,%2,%3,%4};" :: "r"(a), "r"(x), "r"(y), "r"(z), "r"(w));
}
__device__ __forceinline__ void cpasync16(unsigned smem, const void* g) {
    asm volatile("cp.async.cg.shared.global [%0], [%1], 16;" :: "r"(smem), "l"(g));
}
__device__ __forceinline__ void cpcommit() { asm volatile("cp.async.commit_group;"); }
__device__ __forceinline__ void cpwait0() { asm volatile("cp.async.wait_group 0;"); }
__device__ __forceinline__ void ldsm4(unsigned& r0, unsigned& r1, unsigned& r2, unsigned& r3, unsigned a) {
    asm volatile("ldmatrix.sync.aligned.m8n8.x4.shared.b16 {%0,%1,%2,%3}, [%4];"
                 : "=r"(r0), "=r"(r1), "=r"(r2), "=r"(r3) : "r"(a));
}
__device__ __forceinline__ void mma16816(float* c, const unsigned* a, unsigned b0, unsigned b1) {
    asm volatile(
        "mma.sync.aligned.m16n8k16.row.col.f32.f16.f16.f32 "
        "{%0,%1,%2,%3}, {%4,%5,%6,%7}, {%8,%9}, {%0,%1,%2,%3};"
        : "+f"(c[0]), "+f"(c[1]), "+f"(c[2]), "+f"(c[3])
        : "r"(a[0]), "r"(a[1]), "r"(a[2]), "r"(a[3]), "r"(b0), "r"(b1));
}

// smem layout: rows padded to 80B (gcd(80,128)=16 -> conflict-free ldmatrix)
#define ASTR 80
#define SM_A 10240             // 128 rows * 80B
#define SM_B 20480             // 256 rows * 80B
#define SM_STG (SM_A + SM_B)        // one stage: A|B = 30720
#define SM_TOT (2*SM_STG)           // double buffered = 61440

// ---------------- fused layer GEMM (round-9 proven: LDG-prefetch A + cp.async B) ----------------
__global__ __launch_bounds__(512) void gemm_mma_kernel(
    int xsel, float* __restrict__ oext, int osel,
    const float* __restrict__ bias, int do_relu, int layer, int zero_deg)
{
    extern __shared__ char smem[];
    const __half* xin = (xsel == 0) ? g_x0h : ((xsel == 1) ? g_x1h : g_x2h);
    __half* outh = (osel == 1) ? g_x1h : g_x2h;
    const __half* bw = g_bh + layer * 131072;

    const unsigned su = sm_u32(smem);

    const int tid = threadIdx.x;
    const int wid = tid >> 5;
    const int lane = tid & 31;
    const int wm = wid & 1;
    const int wn = wid >> 1;
    const int row0 = blockIdx.x * 128;

    const int arow = tid >> 2;
    const int akq = tid & 3;
    const int gr = row0 + arow;
    const bool rok = gr < NN;
    const __half* aggrow = g_acch + (size_t)(rok ? gr : 0) * DD;
    const __half* xrow = xin + (size_t)(rok ? gr : 0) * DD;

    const int brow = tid >> 1;
    const int bkh = (tid & 1) * 16;

    const unsigned aoff = (unsigned)((wm * 64 + (lane & 15)) * ASTR + (lane >> 4) * 16);
    const unsigned boff = (unsigned)((wn * 32 + ((lane >> 4) & 1) * 8 + (lane & 7)) * ASTR
                                     + ((lane >> 3) & 1) * 16);

    float acc[4][4][4];
    #pragma unroll
    for (int i = 0; i < 4; i++)
        #pragma unroll
        for (int j = 0; j < 4; j++)
            #pragma unroll
            for (int q = 0; q < 4; q++) acc[i][j][q] = 0.f;

    uint4 pa;

    auto ldA = [&](int ck) {
        const int side = ck >> 3;
        const __half* s = (side ? xrow : aggrow) + (ck & 7) * 32 + akq * 8;
        if (rok) pa = *(const uint4*)s;
        else pa = make_uint4(0u, 0u, 0u, 0u);
    };
    auto stsA = [&](int stg) {
        unsigned base = su + (unsigned)stg * SM_STG;
        unsigned off = (unsigned)(arow * ASTR + akq * 16);
        sts128(base + off, pa.x, pa.y, pa.z, pa.w);
    };
    auto cpB = [&](int ck, int stg) {
        unsigned base = su + (unsigned)stg * SM_STG + SM_A;
        unsigned off = (unsigned)(brow * ASTR + bkh * 2);
        size_t go = (size_t)brow * 512 + ck * 32 + bkh;
        cpasync16(base + off, bw + go);
        cpasync16(base + off + 16, bw + go + 8);
        cpcommit();
    };

    ldA(0);
    stsA(0);
    cpB(0, 0);
    ldA(1);

    #pragma unroll 1
    for (int ck = 0; ck < 16; ck++) {
        const int s = ck & 1;
        cpwait0();
        __syncthreads();

        if (ck < 15) {
            stsA(s ^ 1);
            cpB(ck + 1, s ^ 1);
        }
        if (ck < 14) ldA(ck + 2);

        const unsigned sbase = su + (unsigned)s * SM_STG;
        const unsigned suA = sbase;
        const unsigned suB = sbase + SM_A;

        #pragma unroll
        for (int ks = 0; ks < 2; ks++) {
            const unsigned kb = (unsigned)(ks * 32);
            unsigned bh[4][2];
            #pragma unroll
            for (int p = 0; p < 2; p++) {
                ldsm4(bh[2 * p][0], bh[2 * p][1], bh[2 * p + 1][0], bh[2 * p + 1][1],
                      suB + boff + p * (16 * ASTR) + kb);
            }
            #pragma unroll
            for (int mi = 0; mi < 4; mi++) {
                unsigned af[4];
                ldsm4(af[0], af[1], af[2], af[3], suA + aoff + mi * (16 * ASTR) + kb);
                #pragma unroll
                for (int ni = 0; ni < 4; ni++) mma16816(acc[mi][ni], af, bh[ni][0], bh[ni][1]);
            }
        }
    }

    const int gr2 = lane >> 2;
    const int gc2 = (lane & 3) * 2;
    #pragma unroll
    for (int mi = 0; mi < 4; mi++) {
        const int rbase = row0 + wm * 64 + mi * 16 + gr2;
        #pragma unroll
        for (int h = 0; h < 2; h++) {
            const int r = rbase + h * 8;
            if (r < NN) {
                #pragma unroll
                for (int ni = 0; ni < 4; ni++) {
                    const int c = wn * 32 + ni * 8 + gc2;
                    float2 bv = *(const float2*)(bias + c);
                    float v0 = acc[mi][ni][h * 2 + 0] + bv.x;
                    float v1 = acc[mi][ni][h * 2 + 1] + bv.y;
                    if (do_relu) { v0 = fmaxf(v0, 0.f); v1 = fmaxf(v1, 0.f); }
                    if (osel == 0) {
                        *(float2*)(oext + (size_t)r * DD + c) = make_float2(v0, v1);
                    } else {
                        *(unsigned*)(outh + (size_t)r * DD + c) = h2u(__floats2half2_rn(v0, v1));
                    }
                }
            }
        }
    }

    // last layer: re-zero degree counters for the next graph replay
    if (zero_deg && tid < 128) {
        int n = row0 + tid;
        if (n < NN) g_degi[n] = 0;
    }
}

// ---------------- launcher ----------------
extern "C" void kernel_launch(void* const* d_in, const int* in_sizes, int n_in,
                              void* d_out, int out_size) {
    (void)in_sizes; (void)n_in; (void)out_size;
    const void* edge = d_in[0];
    const float* x0 = (const float*)d_in[1];
    const float* Wl[3] = {(const float*)d_in[2], (const float*)d_in[5], (const float*)d_in[8]};
    const float* Wr[3] = {(const float*)d_in[3], (const float*)d_in[6], (const float*)d_in[9]};
    const float* bb[3] = {(const float*)d_in[4], (const float*)d_in[7], (const float*)d_in[10]};
    float* out = (float*)d_out;

    static int inited = 0;
    static cudaStream_t s1;
    static cudaEvent_t evFork, evJoin;
    if (!inited) {
        cudaFuncSetAttribute(gemm_mma_kernel, cudaFuncAttributeMaxDynamicSharedMemorySize, SM_TOT);
        cudaStreamCreateWithFlags(&s1, cudaStreamNonBlocking);
        cudaEventCreateWithFlags(&evFork, cudaEventDisableTiming);
        cudaEventCreateWithFlags(&evJoin, cudaEventDisableTiming);
        inited = 1;
    }

    const int TB = 256;
    const int ecnt = (EE + TB - 1) / TB;
    const int ggrid = (NN + 127) / 128;
    const int agrid = (NN * 32 + TB - 1) / TB;

    // fork: data conversion branch runs concurrently with edge/CSR chain
    cudaEventRecord(evFork, 0);
    cudaStreamWaitEvent(s1, evFork, 0);
    prep_data_kernel<<<PD_TOTAL, TB, 0, s1>>>(x0, Wl[0], Wr[0], Wl[1], Wr[1], Wl[2], Wr[2]);
    cudaEventRecord(evJoin, s1);

    // main chain (default stream)
    prep_edge_kernel<<<ecnt, TB>>>(edge);
    scan_kernel<<<NB, 1024>>>();
    fill_kernel<<<ecnt, TB>>>();

    cudaStreamWaitEvent(0, evJoin, 0);   // join: agg1 needs x0h, gemm needs weights

    aggregate_kernel<<<agrid, TB>>>(0);
    gemm_mma_kernel<<<ggrid, 512, SM_TOT>>>(0, nullptr, 1, bb[0], 1, 0, 0);

    aggregate_kernel<<<agrid, TB>>>(1);
    gemm_mma_kernel<<<ggrid, 512, SM_TOT>>>(1, nullptr, 2, bb[1], 1, 1, 0);

    aggregate_kernel<<<agrid, TB>>>(2);
    gemm_mma_kernel<<<ggrid, 512, SM_TOT>>>(2, out, 0, bb[2], 0, 2, 1);
}